// round 1
// baseline (speedup 1.0000x reference)
#include <cuda_runtime.h>
#include <cuda_bf16.h>
#include <cstdint>

// Problem constants (from reference setup_inputs)
#define NB   64          // batch
#define NT   1000        // time steps
#define NI   512         // input features (K)
#define NO   256         // output features (N)
#define NM   (NB * NT)   // GEMM M dimension = 64000

#define ALPHA 0.95f
#define BETA  0.90f

// Scratch for the projection h[b,t,o] (65.5 MB). __device__ global = allowed scratch.
__device__ float g_h[(size_t)NM * NO];

// ---------------------------------------------------------------------------
// Phase 1: SGEMM  h[m, n] = sum_k A[m, k] * W[n, k]
//   A: (NM, NI) row-major (K contiguous)
//   W: (NO, NI) row-major (K contiguous)
// Tiling: BM=128, BN=128, BK=16, 256 threads, 8x8 per-thread register tile.
// ---------------------------------------------------------------------------
#define BM 128
#define BN 128
#define BK 16
#define TM 8
#define TN 8

__global__ __launch_bounds__(256, 2)
void snn_gemm_kernel(const float* __restrict__ A, const float* __restrict__ W)
{
    __shared__ float As[BK][BM];   // transposed: As[k][m]
    __shared__ float Bs[BK][BN];   // transposed: Bs[k][n]

    const int bn = blockIdx.x * BN;     // 0 or 128
    const int bm = blockIdx.y * BM;     // 0..63872

    const int tid = threadIdx.x;        // 0..255
    const int tx  = tid & 15;           // 0..15 -> n-tile
    const int ty  = tid >> 4;           // 0..15 -> m-tile

    // Loader mapping: tile is 128 rows x 16 k-cols = 512 float4 loads per operand,
    // 256 threads -> 2 float4 per thread per operand.
    const int l_row0 = tid >> 2;              // 0..63   (phase 0 rows 0..63? no:)
    // v = tid + phase*256 ; row = v/4 (0..127), col4 = (v%4)*4
    const float* Ablk = A + (size_t)bm * NI;
    const float* Wblk = W + (size_t)bn * NI;
    (void)l_row0;

    float acc[TM][TN];
#pragma unroll
    for (int i = 0; i < TM; i++)
#pragma unroll
        for (int j = 0; j < TN; j++)
            acc[i][j] = 0.0f;

    for (int k0 = 0; k0 < NI; k0 += BK) {
        // ---- load A tile and W tile into smem (transposed) ----
#pragma unroll
        for (int phase = 0; phase < 2; phase++) {
            int v    = tid + phase * 256;
            int row  = v >> 2;           // 0..127
            int col4 = (v & 3) << 2;     // 0,4,8,12

            float4 av = *reinterpret_cast<const float4*>(Ablk + (size_t)row * NI + k0 + col4);
            As[col4 + 0][row] = av.x;
            As[col4 + 1][row] = av.y;
            As[col4 + 2][row] = av.z;
            As[col4 + 3][row] = av.w;

            float4 wv = *reinterpret_cast<const float4*>(Wblk + (size_t)row * NI + k0 + col4);
            Bs[col4 + 0][row] = wv.x;
            Bs[col4 + 1][row] = wv.y;
            Bs[col4 + 2][row] = wv.z;
            Bs[col4 + 3][row] = wv.w;
        }
        __syncthreads();

        // ---- inner product over the BK slice ----
#pragma unroll
        for (int k = 0; k < BK; k++) {
            float a[TM], b[TN];
            float4 a0 = *reinterpret_cast<const float4*>(&As[k][ty * TM]);
            float4 a1 = *reinterpret_cast<const float4*>(&As[k][ty * TM + 4]);
            a[0]=a0.x; a[1]=a0.y; a[2]=a0.z; a[3]=a0.w;
            a[4]=a1.x; a[5]=a1.y; a[6]=a1.z; a[7]=a1.w;
            float4 b0 = *reinterpret_cast<const float4*>(&Bs[k][tx * TN]);
            float4 b1 = *reinterpret_cast<const float4*>(&Bs[k][tx * TN + 4]);
            b[0]=b0.x; b[1]=b0.y; b[2]=b0.z; b[3]=b0.w;
            b[4]=b1.x; b[5]=b1.y; b[6]=b1.z; b[7]=b1.w;
#pragma unroll
            for (int i = 0; i < TM; i++)
#pragma unroll
                for (int j = 0; j < TN; j++)
                    acc[i][j] = fmaf(a[i], b[j], acc[i][j]);
        }
        __syncthreads();
    }

    // ---- epilogue: write h tile (coalesced float4) ----
    float* C = g_h + (size_t)bm * NO + bn;
#pragma unroll
    for (int i = 0; i < TM; i++) {
        size_t roff = (size_t)(ty * TM + i) * NO + tx * TN;
        float4 v0 = make_float4(acc[i][0], acc[i][1], acc[i][2], acc[i][3]);
        float4 v1 = make_float4(acc[i][4], acc[i][5], acc[i][6], acc[i][7]);
        *reinterpret_cast<float4*>(C + roff)     = v0;
        *reinterpret_cast<float4*>(C + roff + 4) = v1;
    }
}

// ---------------------------------------------------------------------------
// Phase 2: sequential scan over t per (b, o) channel.
//   flt_new = ALPHA*flt + h_t ; out_new = BETA*out + flt_old ; emit out_new
// grid: (2, 64) -> 128 CTAs of 128 threads; thread handles one (b, o).
// ---------------------------------------------------------------------------
__global__ __launch_bounds__(128)
void snn_scan_kernel(float* __restrict__ out)
{
    const int b = blockIdx.y;                           // 0..63
    const int o = blockIdx.x * 128 + threadIdx.x;       // 0..255

    const float* hp = g_h + (size_t)b * NT * NO + o;
    float*       op = out + (size_t)b * NT * NO + o;

    float flt = 0.0f;
    float acc = 0.0f;

#pragma unroll 4
    for (int t = 0; t < NT; t++) {
        float hv = hp[(size_t)t * NO];
        float new_acc = fmaf(BETA, acc, flt);   // uses OLD flt
        flt = fmaf(ALPHA, flt, hv);
        acc = new_acc;
        op[(size_t)t * NO] = acc;
    }
}

extern "C" void kernel_launch(void* const* d_in, const int* in_sizes, int n_in,
                              void* d_out, int out_size)
{
    const float* inputs = (const float*)d_in[0];   // (64, 1000, 512) f32
    const float* W      = (const float*)d_in[1];   // (256, 512) f32
    // d_in[2] = nb_steps (int32, == 1000) — compile-time constant here.
    float* out = (float*)d_out;                    // (64, 1000, 256) f32
    (void)in_sizes; (void)n_in; (void)out_size;

    dim3 ggrid(NO / BN, NM / BM);   // (2, 500)
    snn_gemm_kernel<<<ggrid, 256>>>(inputs, W);

    dim3 sgrid(2, NB);              // (2, 64)
    snn_scan_kernel<<<sgrid, 128>>>(out);
}

// round 5
// speedup vs baseline: 2.1320x; 2.1320x over previous
#include <cuda_runtime.h>
#include <cuda_bf16.h>
#include <cstdint>

// ---------------------------------------------------------------- constants
#define NB   64
#define NT   1000
#define NI   512          // K
#define NO   256          // N
#define NM   (NB * NT)    // 64000 (M)

#define ALPHA 0.95f
#define BETA  0.90f

// ---------------------------------------------------------------- scratch
// A2 = [A_hi | A_lo] per row: (NM, 1024) bf16 = 131 MB
__device__ __align__(256) __nv_bfloat16 g_A2[(size_t)NM * 1024];
__device__ __align__(256) __nv_bfloat16 g_Whi[NO * NI];
__device__ __align__(256) __nv_bfloat16 g_Wlo[NO * NI];
__device__ __align__(256) float         g_h[(size_t)NM * NO];

// ---------------------------------------------------------------- helpers
__device__ __forceinline__ uint32_t smem_u32(const void* p) {
    uint32_t a;
    asm("{ .reg .u64 t; cvta.to.shared.u64 t, %1; cvt.u32.u64 %0, t; }"
        : "=r"(a) : "l"(p));
    return a;
}
__device__ __forceinline__ void cpasync16(uint32_t s, const void* g) {
    asm volatile("cp.async.cg.shared.global [%0], [%1], 16;\n" :: "r"(s), "l"(g));
}
#define CP_COMMIT()  asm volatile("cp.async.commit_group;" ::: "memory")
#define CP_WAIT(n)   asm volatile("cp.async.wait_group %0;" :: "n"(n) : "memory")

__device__ __forceinline__ void ldsm_x4(uint32_t* r, uint32_t addr) {
    asm volatile("ldmatrix.sync.aligned.m8n8.x4.shared.b16 {%0,%1,%2,%3}, [%4];"
                 : "=r"(r[0]), "=r"(r[1]), "=r"(r[2]), "=r"(r[3]) : "r"(addr));
}
__device__ __forceinline__ void ldsm_x2(uint32_t* r, uint32_t addr) {
    asm volatile("ldmatrix.sync.aligned.m8n8.x2.shared.b16 {%0,%1}, [%2];"
                 : "=r"(r[0]), "=r"(r[1]) : "r"(addr));
}
__device__ __forceinline__ void mma16816(float* d, const uint32_t* a, const uint32_t* b) {
    asm volatile(
        "mma.sync.aligned.m16n8k16.row.col.f32.bf16.bf16.f32 "
        "{%0,%1,%2,%3}, {%4,%5,%6,%7}, {%8,%9}, {%0,%1,%2,%3};"
        : "+f"(d[0]), "+f"(d[1]), "+f"(d[2]), "+f"(d[3])
        : "r"(a[0]), "r"(a[1]), "r"(a[2]), "r"(a[3]), "r"(b[0]), "r"(b[1]));
}

// ---------------------------------------------------------------- convert A
__global__ __launch_bounds__(256)
void snn_convA(const float* __restrict__ in) {
    size_t idx = (size_t)blockIdx.x * 256 + threadIdx.x;  // 4,096,000 threads
    size_t e0  = idx * 8;
    float4 v0 = *reinterpret_cast<const float4*>(in + e0);
    float4 v1 = *reinterpret_cast<const float4*>(in + e0 + 4);
    float xs[8] = {v0.x, v0.y, v0.z, v0.w, v1.x, v1.y, v1.z, v1.w};
    __align__(16) __nv_bfloat16 hi[8];
    __align__(16) __nv_bfloat16 lo[8];
#pragma unroll
    for (int i = 0; i < 8; i++) {
        hi[i] = __float2bfloat16(xs[i]);
        lo[i] = __float2bfloat16(xs[i] - __bfloat162float(hi[i]));
    }
    size_t m = e0 >> 9;          // /512
    size_t k = e0 & 511;
    *reinterpret_cast<uint4*>(g_A2 + m * 1024 + k)       = *reinterpret_cast<uint4*>(hi);
    *reinterpret_cast<uint4*>(g_A2 + m * 1024 + 512 + k) = *reinterpret_cast<uint4*>(lo);
}

__global__ __launch_bounds__(256)
void snn_convW(const float* __restrict__ W) {
    size_t idx = (size_t)blockIdx.x * 256 + threadIdx.x;  // 16384 threads
    size_t e0  = idx * 8;
    float4 v0 = *reinterpret_cast<const float4*>(W + e0);
    float4 v1 = *reinterpret_cast<const float4*>(W + e0 + 4);
    float xs[8] = {v0.x, v0.y, v0.z, v0.w, v1.x, v1.y, v1.z, v1.w};
    __align__(16) __nv_bfloat16 hi[8];
    __align__(16) __nv_bfloat16 lo[8];
#pragma unroll
    for (int i = 0; i < 8; i++) {
        hi[i] = __float2bfloat16(xs[i]);
        lo[i] = __float2bfloat16(xs[i] - __bfloat162float(hi[i]));
    }
    *reinterpret_cast<uint4*>(g_Whi + e0) = *reinterpret_cast<uint4*>(hi);
    *reinterpret_cast<uint4*>(g_Wlo + e0) = *reinterpret_cast<uint4*>(lo);
}

// ---------------------------------------------------------------- GEMM (mma.sync bf16 3-pass)
// BM=128, BN=128, BK=32, 16 chunks, double-buffered cp.async.
// 8 warps: warpM = wid/4 (2), warpN = wid%4 (4); warp tile 64x32.
#define KCHUNKS   16
#define OFF_AHI   0
#define OFF_ALO   (8 * 1024)
#define OFF_WHI   (16 * 1024)
#define OFF_WLO   (24 * 1024)
#define STAGE_SZ  (32 * 1024)
#define SMEM_DYN  (2 * STAGE_SZ)

// smem tile layout: 128 rows x 32 bf16 (64B/row), seg (16B unit) swizzled:
// off(row, seg) = row*64 + ((seg ^ (row & 3)) << 4)
__device__ __forceinline__ uint32_t swz_off(int row, int seg) {
    return (uint32_t)(row * 64 + ((seg ^ (row & 3)) << 4));
}

__device__ __forceinline__ void load_chunk(uint32_t st, int bm, int bn, int kc) {
    const int tid = threadIdx.x;
#pragma unroll
    for (int i = 0; i < 2; i++) {
        int idx = tid * 2 + i;        // 0..511
        int row = idx >> 2;           // 0..127
        int seg = idx & 3;            // 16B segment
        uint32_t so = swz_off(row, seg);
        const __nv_bfloat16* Ar = g_A2 + (size_t)(bm + row) * 1024 + kc * 32 + seg * 8;
        cpasync16(st + OFF_AHI + so, Ar);
        cpasync16(st + OFF_ALO + so, Ar + 512);
        const size_t wroff = (size_t)(bn + row) * 512 + kc * 32 + seg * 8;
        cpasync16(st + OFF_WHI + so, g_Whi + wroff);
        cpasync16(st + OFF_WLO + so, g_Wlo + wroff);
    }
}

__global__ __launch_bounds__(256, 2)
void snn_gemm_mma() {
    extern __shared__ char smem_raw[];
    const uint32_t sbase = smem_u32(smem_raw);
    const uint32_t stg[2] = {sbase, sbase + STAGE_SZ};

    const int tid   = threadIdx.x;
    const int lane  = tid & 31;
    const int wid   = tid >> 5;
    const int warpM = wid >> 2;       // 0..1
    const int warpN = wid & 3;        // 0..3
    const int bm    = blockIdx.x * 128;
    const int bn    = blockIdx.y * 128;

    float c[4][4][4];
#pragma unroll
    for (int mt = 0; mt < 4; mt++)
#pragma unroll
        for (int nt = 0; nt < 4; nt++)
#pragma unroll
            for (int r = 0; r < 4; r++)
                c[mt][nt][r] = 0.0f;

    // ldmatrix per-lane address components (invariant across chunks)
    const int a_row = warpM * 64 + (lane & 15);   // + mt*16
    const int a_sel = lane >> 4;                  // seg half within k16
    const int bl    = lane & 15;
    const int b_row = warpN * 32 + (bl & 7);      // + nt*8
    const int b_sel = (bl >> 3) & 1;

    load_chunk(stg[0], bm, bn, 0);
    CP_COMMIT();

    for (int kc = 0; kc < KCHUNKS; kc++) {
        const uint32_t cur = stg[kc & 1];
        if (kc < KCHUNKS - 1) {
            load_chunk(stg[(kc + 1) & 1], bm, bn, kc + 1);
            CP_COMMIT();
            CP_WAIT(1);
        } else {
            CP_WAIT(0);
        }
        __syncthreads();

#pragma unroll
        for (int kk = 0; kk < 2; kk++) {
            uint32_t afh[4][4], afl[4][4];
#pragma unroll
            for (int mt = 0; mt < 4; mt++) {
                uint32_t so = swz_off(a_row + mt * 16, 2 * kk + a_sel);
                ldsm_x4(afh[mt], cur + OFF_AHI + so);
                ldsm_x4(afl[mt], cur + OFF_ALO + so);
            }
            uint32_t bfh[4][2], bfl[4][2];
#pragma unroll
            for (int nt = 0; nt < 4; nt++) {
                uint32_t so = swz_off(b_row + nt * 8, 2 * kk + b_sel);
                ldsm_x2(bfh[nt], cur + OFF_WHI + so);
                ldsm_x2(bfl[nt], cur + OFF_WLO + so);
            }
#pragma unroll
            for (int mt = 0; mt < 4; mt++)
#pragma unroll
                for (int nt = 0; nt < 4; nt++) {
                    mma16816(c[mt][nt], afh[mt], bfh[nt]);
                    mma16816(c[mt][nt], afh[mt], bfl[nt]);
                    mma16816(c[mt][nt], afl[mt], bfh[nt]);
                }
        }
        __syncthreads();
    }

    // epilogue: fragment -> g_h (float2 stores)
    const int g = lane >> 2;
    const int q = lane & 3;
#pragma unroll
    for (int mt = 0; mt < 4; mt++) {
#pragma unroll
        for (int nt = 0; nt < 4; nt++) {
            int r0  = bm + warpM * 64 + mt * 16 + g;
            int col = bn + warpN * 32 + nt * 8 + q * 2;
            *reinterpret_cast<float2*>(g_h + (size_t)r0 * NO + col)
                = make_float2(c[mt][nt][0], c[mt][nt][1]);
            *reinterpret_cast<float2*>(g_h + (size_t)(r0 + 8) * NO + col)
                = make_float2(c[mt][nt][2], c[mt][nt][3]);
        }
    }
}

// ---------------------------------------------------------------- scan
__global__ __launch_bounds__(128)
void snn_scan(float* __restrict__ out) {
    const int b = blockIdx.y;
    const int o = blockIdx.x * 128 + threadIdx.x;
    const float* hp = g_h + (size_t)b * NT * NO + o;
    float*       op = out + (size_t)b * NT * NO + o;

    float flt = 0.0f, acc = 0.0f;
    for (int t = 0; t < NT; t += 20) {
        float hv[20];
#pragma unroll
        for (int j = 0; j < 20; j++) hv[j] = hp[(size_t)(t + j) * NO];
#pragma unroll
        for (int j = 0; j < 20; j++) {
            float na = fmaf(BETA, acc, flt);   // uses OLD flt
            flt = fmaf(ALPHA, flt, hv[j]);
            acc = na;
            op[(size_t)(t + j) * NO] = acc;
        }
    }
}

// ---------------------------------------------------------------- launch
extern "C" void kernel_launch(void* const* d_in, const int* in_sizes, int n_in,
                              void* d_out, int out_size) {
    const float* inputs = (const float*)d_in[0];   // (64,1000,512) f32
    const float* W      = (const float*)d_in[1];   // (256,512) f32
    float* out          = (float*)d_out;           // (64,1000,256) f32
    (void)in_sizes; (void)n_in; (void)out_size;

    cudaFuncSetAttribute(snn_gemm_mma, cudaFuncAttributeMaxDynamicSharedMemorySize, SMEM_DYN);

    snn_convA<<<16000, 256>>>(inputs);
    snn_convW<<<64, 256>>>(W);
    snn_gemm_mma<<<dim3(500, 2), 256, SMEM_DYN>>>();
    snn_scan<<<dim3(2, NB), 128>>>(out);
}